// round 2
// baseline (speedup 1.0000x reference)
#include <cuda_runtime.h>
#include <math.h>

#define S_DIM 512
#define B_DIM 32
#define T_DIM 1024
#define E_DIM 512
#define Q_DIM 128
#define SPB   16         // s-rows per block in kernel C
#define TCH   32         // t-chunk (weight tile width)
#define CUT   16.0f      // exponent cutoff: exp(-16) ~ 1.1e-7

// Scratch (allocation-free rule: __device__ globals). Layout [B][S].
__device__ float g_mr[B_DIM * S_DIM];    // mean_raw = exp(q.w0 + b0)
__device__ float g_sd[B_DIM * S_DIM];    // std      = exp(q.w1 + b1)
__device__ float g_mean[B_DIM * S_DIM];  // position + cumsum(mean_raw)/20

// Packed f32x2 helpers (Blackwell FFMA2 — only reachable via PTX).
static __device__ __forceinline__ unsigned long long pack2f(float a, float b) {
    unsigned long long r;
    asm("mov.b64 %0, {%1, %2};" : "=l"(r) : "f"(a), "f"(b));
    return r;
}
static __device__ __forceinline__ unsigned long long fma2(
    unsigned long long a, unsigned long long b, unsigned long long c) {
    unsigned long long d;
    asm("fma.rn.f32x2 %0, %1, %2, %3;" : "=l"(d) : "l"(a), "l"(b), "l"(c));
    return d;
}

// ---------------------------------------------------------------------------
// Kernel A: one warp per FOUR (s,b) rows. 4 independent q loads (MLP=4),
// 8 interleaved shuffle-reduce chains, then exp on lane 0.
// ---------------------------------------------------------------------------
__global__ void ga_qdot(const float* __restrict__ q,
                        const float* __restrict__ W,
                        const float* __restrict__ bias) {
    int warp = (blockIdx.x * blockDim.x + threadIdx.x) >> 5;
    int lane = threadIdx.x & 31;
    int r0   = warp * 4;                       // row r = s*B + b
    if (r0 >= S_DIM * B_DIM) return;

    float4 a0 = ((const float4*)W)[lane];
    float4 a1 = ((const float4*)(W + Q_DIM))[lane];

    float d0[4], d1[4];
    #pragma unroll
    for (int k = 0; k < 4; k++) {
        float4 v = ((const float4*)(q + (size_t)(r0 + k) * Q_DIM))[lane];
        d0[k] = v.x * a0.x + v.y * a0.y + v.z * a0.z + v.w * a0.w;
        d1[k] = v.x * a1.x + v.y * a1.y + v.z * a1.z + v.w * a1.w;
    }
    #pragma unroll
    for (int off = 16; off; off >>= 1) {
        #pragma unroll
        for (int k = 0; k < 4; k++) {
            d0[k] += __shfl_xor_sync(0xFFFFFFFFu, d0[k], off);
            d1[k] += __shfl_xor_sync(0xFFFFFFFFu, d1[k], off);
        }
    }
    if (lane == 0) {
        float b0 = bias[0], b1 = bias[1];
        #pragma unroll
        for (int k = 0; k < 4; k++) {
            int r = r0 + k;
            int s = r >> 5;       // r / B_DIM
            int b = r & 31;       // r % B_DIM
            g_mr[b * S_DIM + s] = expf(d0[k] + b0);
            g_sd[b * S_DIM + s] = expf(d1[k] + b1);
        }
    }
}

// ---------------------------------------------------------------------------
// Kernel B: one block per b, 512 threads, shuffle-based inclusive scan.
// ---------------------------------------------------------------------------
__global__ void ga_scan(const float* __restrict__ pos,
                        float* __restrict__ out_mean) {
    int b = blockIdx.x;
    int s = threadIdx.x;           // 512 threads
    int lane = s & 31, wid = s >> 5;
    __shared__ float wsum[16];

    float v = g_mr[b * S_DIM + s];
    #pragma unroll
    for (int off = 1; off < 32; off <<= 1) {
        float y = __shfl_up_sync(0xFFFFFFFFu, v, off);
        if (lane >= off) v += y;
    }
    if (lane == 31) wsum[wid] = v;
    __syncthreads();
    if (wid == 0) {
        float w = (lane < 16) ? wsum[lane] : 0.0f;
        #pragma unroll
        for (int off = 1; off < 16; off <<= 1) {
            float y = __shfl_up_sync(0xFFFFFFFFu, w, off);
            if (lane >= off) w += y;
        }
        if (lane < 16) wsum[lane] = w;
    }
    __syncthreads();
    float base = wid ? wsum[wid - 1] : 0.0f;
    float m = pos[s * B_DIM + b] + (v + base) * 0.05f;
    g_mean[b * S_DIM + s]   = m;
    out_mean[s * B_DIM + b] = m;
}

// ---------------------------------------------------------------------------
// Kernel C: windowed Gaussian attention with union-window register blocking.
// Block = (SPB=16 s-rows, batch b), 128 threads: thread t owns E elems
// [4t, 4t+4). The union t-range over the 16 s-rows (~14 rows) is loaded ONCE
// per block; each row is FMA'd into 16 register accumulators via packed
// fma.rn.f32x2 with (w,w)-packed weights staged in shared.
// ---------------------------------------------------------------------------
__global__ void __launch_bounds__(128) ga_ctx(const float* __restrict__ emb,
                                              const float* __restrict__ mask,
                                              float* __restrict__ out) {
    int b   = blockIdx.y;
    int s0  = blockIdx.x * SPB;
    int tid = threadIdx.x;

    __shared__ float smean[SPB];
    __shared__ float sstd[SPB];
    __shared__ unsigned long long sw2[SPB][TCH];   // packed (w,w)

    if (tid < SPB) {
        smean[tid] = g_mean[b * S_DIM + s0 + tid];
        sstd[tid]  = g_sd[b * S_DIM + s0 + tid];
    }
    __syncthreads();

    // Union window over the 16 s-rows (uniform computation, all from shared).
    int tlo = T_DIM, thi = -1;
    #pragma unroll 4
    for (int i = 0; i < SPB; i++) {
        float mean = smean[i];
        float hw   = sqrtf(CUT / sstd[i]);
        int lo = (int)fmaxf(0.0f, ceilf(mean - hw));
        int hi = (int)fminf((float)(T_DIM - 1), floorf(mean + hw));
        tlo = min(tlo, lo);
        thi = max(thi, hi);
    }

    ulonglong2 acc[SPB];
    #pragma unroll
    for (int i = 0; i < SPB; i++) { acc[i].x = 0ull; acc[i].y = 0ull; }

    for (int tb = tlo; tb <= thi; tb += TCH) {
        int n = min(TCH, thi - tb + 1);
        __syncthreads();
        // Fill SPB*TCH = 512 weights: 128 threads x 4.
        #pragma unroll
        for (int i = 0; i < 4; i++) {
            int idx = tid + i * 128;          // 0..511
            int si  = idx >> 5;               // / TCH
            int tj  = idx & (TCH - 1);
            float wv = 0.0f;
            if (tj < n) {
                int   t = tb + tj;
                float d = smean[si] - (float)t;
                wv = __expf(-sstd[si] * d * d) * mask[t * B_DIM + b];
            }
            sw2[si][tj] = pack2f(wv, wv);
        }
        __syncthreads();

        const float* ep = emb + ((size_t)tb * B_DIM + b) * E_DIM + tid * 4;
        for (int j = 0; j < n; j++) {
            ulonglong2 v = *(const ulonglong2*)ep;
            #pragma unroll
            for (int si = 0; si < SPB; si++) {
                unsigned long long w2 = sw2[si][j];   // broadcast LDS.64
                acc[si].x = fma2(v.x, w2, acc[si].x);
                acc[si].y = fma2(v.y, w2, acc[si].y);
            }
            ep += (size_t)B_DIM * E_DIM;
        }
    }

    #pragma unroll
    for (int si = 0; si < SPB; si++) {
        *(ulonglong2*)(out + ((size_t)(s0 + si) * B_DIM + b) * E_DIM + tid * 4) = acc[si];
    }
}

// ---------------------------------------------------------------------------
extern "C" void kernel_launch(void* const* d_in, const int* in_sizes, int n_in,
                              void* d_out, int out_size) {
    const float* query = (const float*)d_in[0];  // [S,B,Q]
    const float* emb   = (const float*)d_in[1];  // [T,B,E]
    const float* mask  = (const float*)d_in[2];  // [T,B]
    const float* pos   = (const float*)d_in[3];  // [S,B]
    const float* W     = (const float*)d_in[4];  // [2,Q]
    const float* bias  = (const float*)d_in[5];  // [2]

    float* out_ctx  = (float*)d_out;                                  // [S,B,E]
    float* out_mean = (float*)d_out + (size_t)S_DIM * B_DIM * E_DIM;  // [S,B]

    // A: 4096 warps (4 rows each), 8 warps/block
    ga_qdot<<<(S_DIM * B_DIM) / 4 / 8, 256>>>(query, W, bias);
    // B: one block per batch
    ga_scan<<<B_DIM, S_DIM>>>(pos, out_mean);
    // C: (S/SPB, B) blocks of 128 threads
    dim3 grid(S_DIM / SPB, B_DIM);
    ga_ctx<<<grid, 128>>>(emb, mask, out_ctx);
}